// round 12
// baseline (speedup 1.0000x reference)
#include <cuda_runtime.h>
#include <cuda_bf16.h>
#include <cuda_fp16.h>
#include <cstdint>

#define SDIM 256
#define EDIM 32
#define VDIM 64
#define NMOL 64
#define NAF  16
#define NBT  5
#define MAXN 2048
#define ETILE 128
#define QROWS 34
#define GPITCH 34

// ---------------- device scratch ----------------
__device__ float  g_sh[MAXN * SDIM];
__device__ __half g_Th[MAXN * SDIM];       // T = s_h @ W0' in fp16
__device__ float  g_raw[MAXN * 3];
__device__ float  g_sums[NMOL * 3];
__device__ float  g_cnt[NMOL];
__device__ int    g_map[MAXN * MAXN];
__device__ float  g_wbw0[EDIM * SDIM];     // Wb @ W0'
__device__ float  g_cvec[SDIM];            // bb @ W0' + b0

__device__ __forceinline__ float silu_f(float x) {
    return __fdividef(x, 1.0f + __expf(-x));
}
__device__ __forceinline__ float silu_t(float x) {
    float h = 0.5f * x;
    float t;
    asm("tanh.approx.f32 %0, %1;" : "=f"(t) : "f"(h));
    return fmaf(h, t, h);
}

// ---------------- k0: init ----------------
__global__ void init_kernel(int N) {
    int idx = blockIdx.x * blockDim.x + threadIdx.x;
    int total = N * N;
    for (int i = idx; i < total; i += gridDim.x * blockDim.x) g_map[i] = -1;
    if (idx < NMOL * 3) g_sums[idx] = 0.0f;
    if (idx < NMOL)     g_cnt[idx]  = 0.0f;
}

// ---------------- k1: fused node work (+foldw tail blocks) ----------------
__global__ __launch_bounds__(256) void node_fold_kernel(
    const float* __restrict__ s, const float* __restrict__ Ws,
    const float* __restrict__ bs, const float* __restrict__ W0,
    const float* __restrict__ Wa, const float* __restrict__ ba,
    const float* __restrict__ Wb, const float* __restrict__ bb,
    const float* __restrict__ b0,
    float* __restrict__ out_atoms, int N, int nodeBlocks)
{
    if (blockIdx.x >= nodeBlocks) {
        int c = threadIdx.x;
        int r = blockIdx.x - nodeBlocks;
        const float* xrow = (r < EDIM) ? (Wb + r * SDIM) : bb;
        float a0 = 0, a1 = 0, a2 = 0, a3 = 0, a4 = 0, a5 = 0, a6 = 0, a7 = 0;
        for (int m = 0; m < SDIM; m += 8) {
            float x0 = xrow[m+0], x1 = xrow[m+1], x2 = xrow[m+2], x3 = xrow[m+3];
            float x4 = xrow[m+4], x5 = xrow[m+5], x6 = xrow[m+6], x7 = xrow[m+7];
            a0 += x0 * W0[(m+0)*SDIM+c]; a1 += x1 * W0[(m+1)*SDIM+c];
            a2 += x2 * W0[(m+2)*SDIM+c]; a3 += x3 * W0[(m+3)*SDIM+c];
            a4 += x4 * W0[(m+4)*SDIM+c]; a5 += x5 * W0[(m+5)*SDIM+c];
            a6 += x6 * W0[(m+6)*SDIM+c]; a7 += x7 * W0[(m+7)*SDIM+c];
        }
        float acc = ((a0+a1)+(a2+a3)) + ((a4+a5)+(a6+a7));
        if (r < EDIM) g_wbw0[r * SDIM + c] = acc;
        else          g_cvec[c] = acc + b0[c];
        return;
    }

    __shared__ float sX[16 * 256];
    __shared__ float sW[32 * 256];
    int tid = threadIdx.x, lane = tid & 31, wp = tid >> 5;
    int row0 = blockIdx.x * 16;

    for (int idx = tid; idx < 16 * 256; idx += 256) {
        int g = row0 * 256 + idx;
        sX[idx] = (g < N * 256) ? s[g] : 0.0f;
    }

    float acc[8][2];
#pragma unroll
    for (int u = 0; u < 8; u++) {
        float b = bs[lane + 32 * u];
        acc[u][0] = b; acc[u][1] = b;
    }
    for (int kc = 0; kc < 8; kc++) {
        __syncthreads();
        for (int idx = tid; idx < 8192; idx += 256)
            sW[idx] = Ws[kc * 32 * 256 + idx];
        __syncthreads();
#pragma unroll
        for (int kk = 0; kk < 32; kk++) {
            float w[8];
#pragma unroll
            for (int u = 0; u < 8; u++) w[u] = sW[kk * 256 + lane + 32 * u];
            float x0 = sX[(wp * 2 + 0) * 256 + kc * 32 + kk];
            float x1 = sX[(wp * 2 + 1) * 256 + kc * 32 + kk];
#pragma unroll
            for (int u = 0; u < 8; u++) {
                acc[u][0] += w[u] * x0;
                acc[u][1] += w[u] * x1;
            }
        }
    }
    __syncthreads();
#pragma unroll
    for (int v = 0; v < 2; v++) {
        int r = row0 + wp * 2 + v;
#pragma unroll
        for (int u = 0; u < 8; u++) {
            float z = silu_f(acc[u][v]);
            sX[(wp * 2 + v) * 256 + lane + 32 * u] = z;
            if (r < N) g_sh[r * 256 + lane + 32 * u] = z;
        }
    }

#pragma unroll
    for (int u = 0; u < 8; u++) { acc[u][0] = 0.0f; acc[u][1] = 0.0f; }
    for (int kc = 0; kc < 8; kc++) {
        __syncthreads();
        for (int idx = tid; idx < 8192; idx += 256)
            sW[idx] = W0[kc * 32 * 256 + idx];
        __syncthreads();
#pragma unroll
        for (int kk = 0; kk < 32; kk++) {
            float w[8];
#pragma unroll
            for (int u = 0; u < 8; u++) w[u] = sW[kk * 256 + lane + 32 * u];
            float x0 = sX[(wp * 2 + 0) * 256 + kc * 32 + kk];
            float x1 = sX[(wp * 2 + 1) * 256 + kc * 32 + kk];
#pragma unroll
            for (int u = 0; u < 8; u++) {
                acc[u][0] += w[u] * x0;
                acc[u][1] += w[u] * x1;
            }
        }
    }
#pragma unroll
    for (int v = 0; v < 2; v++) {
        int r = row0 + wp * 2 + v;
        if (r < N) {
#pragma unroll
            for (int u = 0; u < 8; u++)
                g_Th[r * 256 + lane + 32 * u] = __float2half_rn(acc[u][v]);
        }
    }

    __syncthreads();
    for (int idx = tid; idx < SDIM * NAF; idx += 256) sW[idx] = Wa[idx];
    __syncthreads();
#pragma unroll
    for (int v = 0; v < 2; v++) {
        int rl = wp * 2 + v;
        int r = row0 + rl;
        float a[NAF];
#pragma unroll
        for (int q = 0; q < NAF; q++) a[q] = 0.0f;
#pragma unroll
        for (int m = 0; m < 8; m++) {
            int c = lane + 32 * m;
            float x = sX[rl * 256 + c];
#pragma unroll
            for (int q = 0; q < NAF; q++) a[q] += x * sW[c * NAF + q];
        }
#pragma unroll
        for (int q = 0; q < NAF; q++) {
#pragma unroll
            for (int off = 16; off; off >>= 1)
                a[q] += __shfl_xor_sync(0xffffffffu, a[q], off);
        }
        if (r < N && lane < NAF)
            out_atoms[(size_t)r * NAF + lane] = a[lane] + ba[lane];
    }
}

// ---------------- k2: scatter + coords sums ----------------
__global__ void prep_kernel(const int* __restrict__ eidx,
                            const float* __restrict__ v, const float* __restrict__ p,
                            const float* __restrict__ Wc, const int* __restrict__ batch,
                            int N, int E, int scatBlocks)
{
    int tid = threadIdx.x;
    if ((int)blockIdx.x < scatBlocks) {
        int k = blockIdx.x * 256 + tid;
        if (k < E) {
            int j = eidx[k];
            int i = eidx[E + k];
            atomicMax(&g_map[j * N + i], k);
        }
        return;
    }
    int n = (blockIdx.x - scatBlocks) * 8 + (tid >> 5);
    int lane = tid & 31;
    if (n >= N) return;
    const float* vb = v + (size_t)n * 3 * VDIM;
    float w0 = Wc[lane], w1 = Wc[32 + lane];
    float a0 = vb[lane] * w0 + vb[32 + lane] * w1;
    float a1 = vb[64 + lane] * w0 + vb[96 + lane] * w1;
    float a2 = vb[128 + lane] * w0 + vb[160 + lane] * w1;
#pragma unroll
    for (int off = 16; off; off >>= 1) {
        a0 += __shfl_xor_sync(0xffffffffu, a0, off);
        a1 += __shfl_xor_sync(0xffffffffu, a1, off);
        a2 += __shfl_xor_sync(0xffffffffu, a2, off);
    }
    if (lane == 0) {
        int b = batch[n];
        float r0 = p[n * 3 + 0] + a0;
        float r1 = p[n * 3 + 1] + a1;
        float r2 = p[n * 3 + 2] + a2;
        g_raw[n * 3 + 0] = r0; g_raw[n * 3 + 1] = r1; g_raw[n * 3 + 2] = r2;
        atomicAdd(&g_sums[b * 3 + 0], r0);
        atomicAdd(&g_sums[b * 3 + 1], r1);
        atomicAdd(&g_sums[b * 3 + 2], r2);
        atomicAdd(&g_cnt[b], 1.0f);
    }
}

// ---------------- k3 (PROFILED): fused edge network + coords-finalize tail ----------------
#define EDGE_SMEM_BYTES ((4352 + 640 + 256 + 4352 + 512) * 4)

__device__ __forceinline__ unsigned long long dup_f32x2(float x) {
    unsigned long long r;
    asm("mov.b64 %0, {%1, %1};" : "=l"(r) : "r"(__float_as_uint(x)));
    return r;
}
__device__ __forceinline__ void ffma2(unsigned long long& acc,
                                      unsigned long long a, unsigned long long b) {
    asm("fma.rn.f32x2 %0, %1, %2, %0;" : "+l"(acc) : "l"(a), "l"(b));
}
__device__ __forceinline__ float2 unpack2(unsigned long long x) {
    float2 r;
    asm("mov.b64 {%0, %1}, %2;" : "=f"(r.x), "=f"(r.y) : "l"(x));
    return r;
}
__device__ __forceinline__ unsigned long long pack2(float x, float y) {
    unsigned long long r;
    asm("mov.b64 %0, {%1, %2};" : "=l"(r) : "r"(__float_as_uint(x)), "r"(__float_as_uint(y)));
    return r;
}
__device__ __forceinline__ unsigned long long h2_to_f32x2(half2 h) {
    float2 f = __half22float2(h);
    return pack2(f.x, f.y);
}

__global__ __launch_bounds__(256, 4) void edge_kernel(
    const float* __restrict__ e, const int* __restrict__ eidx,
    const int* __restrict__ batch,
    const float* __restrict__ W0, const float* __restrict__ W1,
    const float* __restrict__ b1,
    float* __restrict__ out_bonds, float* __restrict__ out_coords,
    int N, int E, int edgeBlocks)
{
    if ((int)blockIdx.x >= edgeBlocks) {
        int idx = (blockIdx.x - edgeBlocks) * 256 + threadIdx.x;
        if (idx < N * 3) {
            int n = idx / 3, d = idx % 3;
            int b = batch[n];
            float m = g_sums[b * 3 + d] / fmaxf(g_cnt[b], 1.0f);
            out_coords[idx] = g_raw[idx] - m;
        }
        return;
    }

    extern __shared__ float sm[];
    half2* sWh  = (half2*)sm;                  // [34][128] col-pairs (0-31 WbW0, 32 w0d, 33 0)
    half2* sW1h = (half2*)(sm + 4352);         // [5][128]
    float* scv  = sm + 4352 + 640;             // [256]
    float* sg   = scv + 256;                   // [128][GPITCH]
    int*   sI   = (int*)(sg + 128 * GPITCH);
    int*   sJ   = sI + 128;
    int*   sK1  = sJ + 128;
    int*   sK2  = sK1 + 128;

    int tid = threadIdx.x, lane = tid & 31, wp = tid >> 5;
    int e0 = blockIdx.x * ETILE;

    for (int idx = tid; idx < QROWS * 128; idx += 256) {
        int q = idx >> 7, p = idx & 127;
        half2 hv;
        if (q < 32) {
            float2 w = *(const float2*)&g_wbw0[q * 256 + 2 * p];
            hv = __floats2half2_rn(w.x, w.y);
        } else if (q == 32) {
            hv = __floats2half2_rn(W0[256 * 256 + 2 * p], W0[256 * 256 + 2 * p + 1]);
        } else {
            hv = __floats2half2_rn(0.0f, 0.0f);
        }
        sWh[idx] = hv;
    }
    for (int idx = tid; idx < 5 * 128; idx += 256) {
        int b = idx >> 7, p = idx & 127;
        sW1h[idx] = __floats2half2_rn(W1[(2 * p) * NBT + b], W1[(2 * p + 1) * NBT + b]);
    }
    if (tid < 256) scv[tid] = g_cvec[tid];

    if (tid < ETILE) {
        int eg = e0 + tid;
        int i = 0, j = 0, k1 = -1, k2 = -1;
        float dval = 0.0f;
        if (eg < E) {
            j = eidx[eg];
            i = eidx[E + eg];
            k1 = g_map[j * N + i];
            k2 = g_map[i * N + j];
            int bi = batch[i], bj = batch[j];
            float inv_i = 1.0f / fmaxf(g_cnt[bi], 1.0f);
            float inv_j = 1.0f / fmaxf(g_cnt[bj], 1.0f);
            float dx = (g_raw[i*3+0] - g_sums[bi*3+0]*inv_i)
                     - (g_raw[j*3+0] - g_sums[bj*3+0]*inv_j);
            float dy = (g_raw[i*3+1] - g_sums[bi*3+1]*inv_i)
                     - (g_raw[j*3+1] - g_sums[bj*3+1]*inv_j);
            float dz = (g_raw[i*3+2] - g_sums[bi*3+2]*inv_i)
                     - (g_raw[j*3+2] - g_sums[bj*3+2]*inv_j);
            dval = dx * dx + dy * dy + dz * dz;
        }
        sI[tid] = i; sJ[tid] = j; sK1[tid] = k1; sK2[tid] = k2;
        sg[tid * GPITCH + 32] = dval;
        sg[tid * GPITCH + 33] = 0.0f;
    }
    __syncthreads();

    for (int idx = tid; idx < ETILE * 32; idx += 256) {
        int el = idx >> 5, q = idx & 31;
        int k1 = sK1[el], k2 = sK2[el];
        float g1 = (k1 >= 0) ? e[(size_t)k1 * EDIM + q] : 0.0f;
        float g2 = (k2 >= 0) ? e[(size_t)k2 * EDIM + q] : 0.0f;
        sg[el * GPITCH + q] = 0.5f * (g1 + g2);
    }
    __syncthreads();

    // ---- each warp: 16 edges, 4 subpasses of 4 ----
    for (int sub = 0; sub < 4; sub++) {
        int base = wp * 16 + sub * 4;

        unsigned long long acc[4][4];
#pragma unroll
        for (int t = 0; t < 4; t++) {
            unsigned long long cv = *(const unsigned long long*)&scv[2 * lane + 64 * t];
#pragma unroll
            for (int v = 0; v < 4; v++) acc[t][v] = cv;
        }

#pragma unroll 1
        for (int qp = 0; qp < 17; qp++) {
            unsigned long long g0[4], g1[4];
#pragma unroll
            for (int v = 0; v < 4; v++) {
                float2 gp = *(const float2*)&sg[(base + v) * GPITCH + 2 * qp];
                g0[v] = dup_f32x2(gp.x);
                g1[v] = dup_f32x2(gp.y);
            }
#pragma unroll
            for (int t = 0; t < 4; t++) {
                unsigned long long w0f = h2_to_f32x2(sWh[(2 * qp) * 128 + lane + 32 * t]);
                unsigned long long w1f = h2_to_f32x2(sWh[(2 * qp + 1) * 128 + lane + 32 * t]);
#pragma unroll
                for (int v = 0; v < 4; v++) {
                    ffma2(acc[t][v], w0f, g0[v]);
                    ffma2(acc[t][v], w1f, g1[v]);
                }
            }
        }

        // ---- epilogue per edge (fp16 T gathers) ----
#pragma unroll
        for (int v = 0; v < 4; v++) {
            int el = base + v;
            int eg = e0 + el;
            const half2* Ti = (const half2*)(g_Th + (size_t)sI[el] * 256);
            const half2* Tj = (const half2*)(g_Th + (size_t)sJ[el] * 256);

            unsigned long long pbp[NBT];
#pragma unroll
            for (int b = 0; b < NBT; b++) pbp[b] = 0ull;

#pragma unroll
            for (int t = 0; t < 4; t++) {
                int p0 = lane + 32 * t;
                float2 a  = unpack2(acc[t][v]);
                float2 ti = __half22float2(Ti[p0]);
                float2 tj = __half22float2(Tj[p0]);
                float z0 = silu_t(a.x + ti.x + tj.x);
                float z1 = silu_t(a.y + ti.y + tj.y);
                unsigned long long zp = pack2(z0, z1);
#pragma unroll
                for (int b = 0; b < NBT; b++) {
                    unsigned long long w1p = h2_to_f32x2(sW1h[b * 128 + p0]);
                    ffma2(pbp[b], zp, w1p);
                }
            }
            float pb[NBT];
#pragma unroll
            for (int b = 0; b < NBT; b++) {
                float2 u = unpack2(pbp[b]);
                pb[b] = u.x + u.y;
            }
#pragma unroll
            for (int b = 0; b < NBT; b++) {
#pragma unroll
                for (int off = 16; off; off >>= 1)
                    pb[b] += __shfl_xor_sync(0xffffffffu, pb[b], off);
            }
            if (lane == 0 && eg < E) {
#pragma unroll
                for (int b = 0; b < NBT; b++)
                    out_bonds[(size_t)eg * NBT + b] = pb[b] + b1[b];
            }
        }
    }
}

// ---------------- launch ----------------
extern "C" void kernel_launch(void* const* d_in, const int* in_sizes, int n_in,
                              void* d_out, int out_size)
{
    const float* s     = (const float*)d_in[0];
    const float* v     = (const float*)d_in[1];
    const float* p     = (const float*)d_in[2];
    const float* e     = (const float*)d_in[3];
    const int*   batch = (const int*)d_in[4];
    const int*   eidx  = (const int*)d_in[5];
    const float* Ws = (const float*)d_in[6];
    const float* bs = (const float*)d_in[7];
    const float* Wc = (const float*)d_in[8];
    const float* Wa = (const float*)d_in[9];
    const float* ba = (const float*)d_in[10];
    const float* Wb = (const float*)d_in[11];
    const float* bb = (const float*)d_in[12];
    const float* W0 = (const float*)d_in[13];
    const float* b0 = (const float*)d_in[14];
    const float* W1 = (const float*)d_in[15];
    const float* b1 = (const float*)d_in[16];

    int N = in_sizes[0] / SDIM;
    int E = in_sizes[5] / 2;

    float* out        = (float*)d_out;
    float* out_coords = out;
    float* out_atoms  = out + (size_t)N * 3;
    float* out_bonds  = out_atoms + (size_t)N * NAF;

    cudaFuncSetAttribute(edge_kernel, cudaFuncAttributeMaxDynamicSharedMemorySize,
                         EDGE_SMEM_BYTES);

    int init_blocks = (N * N + 1023) / 1024;
    init_kernel<<<init_blocks, 1024>>>(N);

    int nodeBlocks = (N + 15) / 16;
    node_fold_kernel<<<nodeBlocks + EDIM + 1, 256>>>(
        s, Ws, bs, W0, Wa, ba, Wb, bb, b0, out_atoms, N, nodeBlocks);

    int scatBlocks = (E + 255) / 256;
    int coordBlocks = (N + 7) / 8;
    prep_kernel<<<scatBlocks + coordBlocks, 256>>>(
        eidx, v, p, Wc, batch, N, E, scatBlocks);

    int edgeBlocks = (E + ETILE - 1) / ETILE;
    int finBlocks  = (N * 3 + 255) / 256;
    edge_kernel<<<edgeBlocks + finBlocks, 256, EDGE_SMEM_BYTES>>>(
        e, eidx, batch, W0, W1, b1, out_bonds, out_coords, N, E, edgeBlocks);
}

// round 13
// speedup vs baseline: 1.0565x; 1.0565x over previous
#include <cuda_runtime.h>
#include <cuda_bf16.h>
#include <cuda_fp16.h>
#include <cstdint>

#define SDIM 256
#define EDIM 32
#define VDIM 64
#define NMOL 64
#define NAF  16
#define NBT  5
#define MAXN 2048
#define ETILE 128
#define QROWS 34
#define GPITCH 34

// ---------------- device scratch ----------------
__device__ __half g_Th[MAXN * SDIM];       // T = s_h @ W0' in fp16
__device__ float  g_raw[MAXN * 3];
__device__ float  g_sums[NMOL * 3];
__device__ float  g_cnt[NMOL];
__device__ int    g_map[MAXN * MAXN];
__device__ float  g_wbw0[EDIM * SDIM];     // Wb @ W0'
__device__ float  g_cvec[SDIM];            // bb @ W0' + b0

__device__ __forceinline__ float silu_f(float x) {
    return __fdividef(x, 1.0f + __expf(-x));
}
__device__ __forceinline__ float silu_t(float x) {
    float h = 0.5f * x;
    float t;
    asm("tanh.approx.f32 %0, %1;" : "=f"(t) : "f"(h));
    return fmaf(h, t, h);
}

// ---------------- k0: init ----------------
__global__ void init_kernel(int N) {
    int idx = blockIdx.x * blockDim.x + threadIdx.x;
    int total = N * N;
    for (int i = idx; i < total; i += gridDim.x * blockDim.x) g_map[i] = -1;
    if (idx < NMOL * 3) g_sums[idx] = 0.0f;
    if (idx < NMOL)     g_cnt[idx]  = 0.0f;
}

// ---------------- k1: fused node work (+foldw tail blocks) ----------------
__global__ __launch_bounds__(256) void node_fold_kernel(
    const float* __restrict__ s, const float* __restrict__ Ws,
    const float* __restrict__ bs, const float* __restrict__ W0,
    const float* __restrict__ Wa, const float* __restrict__ ba,
    const float* __restrict__ Wb, const float* __restrict__ bb,
    const float* __restrict__ b0,
    float* __restrict__ out_atoms, int N, int nodeBlocks)
{
    if (blockIdx.x >= nodeBlocks) {
        int c = threadIdx.x;
        int r = blockIdx.x - nodeBlocks;
        const float* xrow = (r < EDIM) ? (Wb + r * SDIM) : bb;
        float a0 = 0, a1 = 0, a2 = 0, a3 = 0, a4 = 0, a5 = 0, a6 = 0, a7 = 0;
        for (int m = 0; m < SDIM; m += 8) {
            float x0 = xrow[m+0], x1 = xrow[m+1], x2 = xrow[m+2], x3 = xrow[m+3];
            float x4 = xrow[m+4], x5 = xrow[m+5], x6 = xrow[m+6], x7 = xrow[m+7];
            a0 += x0 * W0[(m+0)*SDIM+c]; a1 += x1 * W0[(m+1)*SDIM+c];
            a2 += x2 * W0[(m+2)*SDIM+c]; a3 += x3 * W0[(m+3)*SDIM+c];
            a4 += x4 * W0[(m+4)*SDIM+c]; a5 += x5 * W0[(m+5)*SDIM+c];
            a6 += x6 * W0[(m+6)*SDIM+c]; a7 += x7 * W0[(m+7)*SDIM+c];
        }
        float acc = ((a0+a1)+(a2+a3)) + ((a4+a5)+(a6+a7));
        if (r < EDIM) g_wbw0[r * SDIM + c] = acc;
        else          g_cvec[c] = acc + b0[c];
        return;
    }

    __shared__ float sX[16 * 256];
    __shared__ float sW[32 * 256];
    int tid = threadIdx.x, lane = tid & 31, wp = tid >> 5;
    int row0 = blockIdx.x * 16;

    for (int idx = tid; idx < 16 * 256; idx += 256) {
        int g = row0 * 256 + idx;
        sX[idx] = (g < N * 256) ? s[g] : 0.0f;
    }

    float acc[8][2];
#pragma unroll
    for (int u = 0; u < 8; u++) {
        float b = bs[lane + 32 * u];
        acc[u][0] = b; acc[u][1] = b;
    }
    for (int kc = 0; kc < 8; kc++) {
        __syncthreads();
        for (int idx = tid; idx < 8192; idx += 256)
            sW[idx] = Ws[kc * 32 * 256 + idx];
        __syncthreads();
#pragma unroll
        for (int kk = 0; kk < 32; kk++) {
            float w[8];
#pragma unroll
            for (int u = 0; u < 8; u++) w[u] = sW[kk * 256 + lane + 32 * u];
            float x0 = sX[(wp * 2 + 0) * 256 + kc * 32 + kk];
            float x1 = sX[(wp * 2 + 1) * 256 + kc * 32 + kk];
#pragma unroll
            for (int u = 0; u < 8; u++) {
                acc[u][0] += w[u] * x0;
                acc[u][1] += w[u] * x1;
            }
        }
    }
    __syncthreads();
#pragma unroll
    for (int v = 0; v < 2; v++) {
#pragma unroll
        for (int u = 0; u < 8; u++) {
            float z = silu_f(acc[u][v]);
            sX[(wp * 2 + v) * 256 + lane + 32 * u] = z;   // s_h stays in smem only
        }
    }

#pragma unroll
    for (int u = 0; u < 8; u++) { acc[u][0] = 0.0f; acc[u][1] = 0.0f; }
    for (int kc = 0; kc < 8; kc++) {
        __syncthreads();
        for (int idx = tid; idx < 8192; idx += 256)
            sW[idx] = W0[kc * 32 * 256 + idx];
        __syncthreads();
#pragma unroll
        for (int kk = 0; kk < 32; kk++) {
            float w[8];
#pragma unroll
            for (int u = 0; u < 8; u++) w[u] = sW[kk * 256 + lane + 32 * u];
            float x0 = sX[(wp * 2 + 0) * 256 + kc * 32 + kk];
            float x1 = sX[(wp * 2 + 1) * 256 + kc * 32 + kk];
#pragma unroll
            for (int u = 0; u < 8; u++) {
                acc[u][0] += w[u] * x0;
                acc[u][1] += w[u] * x1;
            }
        }
    }
#pragma unroll
    for (int v = 0; v < 2; v++) {
        int r = row0 + wp * 2 + v;
        if (r < N) {
#pragma unroll
            for (int u = 0; u < 8; u++)
                g_Th[r * 256 + lane + 32 * u] = __float2half_rn(acc[u][v]);
        }
    }

    __syncthreads();
    for (int idx = tid; idx < SDIM * NAF; idx += 256) sW[idx] = Wa[idx];
    __syncthreads();
#pragma unroll
    for (int v = 0; v < 2; v++) {
        int rl = wp * 2 + v;
        int r = row0 + rl;
        float a[NAF];
#pragma unroll
        for (int q = 0; q < NAF; q++) a[q] = 0.0f;
#pragma unroll
        for (int m = 0; m < 8; m++) {
            int c = lane + 32 * m;
            float x = sX[rl * 256 + c];
#pragma unroll
            for (int q = 0; q < NAF; q++) a[q] += x * sW[c * NAF + q];
        }
#pragma unroll
        for (int q = 0; q < NAF; q++) {
#pragma unroll
            for (int off = 16; off; off >>= 1)
                a[q] += __shfl_xor_sync(0xffffffffu, a[q], off);
        }
        if (r < N && lane < NAF)
            out_atoms[(size_t)r * NAF + lane] = a[lane] + ba[lane];
    }
}

// ---------------- k2: scatter + coords sums ----------------
__global__ void prep_kernel(const int* __restrict__ eidx,
                            const float* __restrict__ v, const float* __restrict__ p,
                            const float* __restrict__ Wc, const int* __restrict__ batch,
                            int N, int E, int scatBlocks)
{
    int tid = threadIdx.x;
    if ((int)blockIdx.x < scatBlocks) {
        int k = blockIdx.x * 256 + tid;
        if (k < E) {
            int j = eidx[k];
            int i = eidx[E + k];
            atomicMax(&g_map[j * N + i], k);
        }
        return;
    }
    int n = (blockIdx.x - scatBlocks) * 8 + (tid >> 5);
    int lane = tid & 31;
    if (n >= N) return;
    const float* vb = v + (size_t)n * 3 * VDIM;
    float w0 = Wc[lane], w1 = Wc[32 + lane];
    float a0 = vb[lane] * w0 + vb[32 + lane] * w1;
    float a1 = vb[64 + lane] * w0 + vb[96 + lane] * w1;
    float a2 = vb[128 + lane] * w0 + vb[160 + lane] * w1;
#pragma unroll
    for (int off = 16; off; off >>= 1) {
        a0 += __shfl_xor_sync(0xffffffffu, a0, off);
        a1 += __shfl_xor_sync(0xffffffffu, a1, off);
        a2 += __shfl_xor_sync(0xffffffffu, a2, off);
    }
    if (lane == 0) {
        int b = batch[n];
        float r0 = p[n * 3 + 0] + a0;
        float r1 = p[n * 3 + 1] + a1;
        float r2 = p[n * 3 + 2] + a2;
        g_raw[n * 3 + 0] = r0; g_raw[n * 3 + 1] = r1; g_raw[n * 3 + 2] = r2;
        atomicAdd(&g_sums[b * 3 + 0], r0);
        atomicAdd(&g_sums[b * 3 + 1], r1);
        atomicAdd(&g_sums[b * 3 + 2], r2);
        atomicAdd(&g_cnt[b], 1.0f);
    }
}

// ---------------- k3 (PROFILED): fused edge network + coords-finalize tail ----------------
#define EDGE_SMEM_BYTES ((4352 + 640 + 256 + 4352 + 512) * 4)

__device__ __forceinline__ unsigned long long dup_f32x2(float x) {
    unsigned long long r;
    asm("mov.b64 %0, {%1, %1};" : "=l"(r) : "r"(__float_as_uint(x)));
    return r;
}
__device__ __forceinline__ void ffma2(unsigned long long& acc,
                                      unsigned long long a, unsigned long long b) {
    asm("fma.rn.f32x2 %0, %1, %2, %0;" : "+l"(acc) : "l"(a), "l"(b));
}
__device__ __forceinline__ float2 unpack2(unsigned long long x) {
    float2 r;
    asm("mov.b64 {%0, %1}, %2;" : "=f"(r.x), "=f"(r.y) : "l"(x));
    return r;
}
__device__ __forceinline__ unsigned long long pack2(float x, float y) {
    unsigned long long r;
    asm("mov.b64 %0, {%1, %2};" : "=l"(r) : "r"(__float_as_uint(x)), "r"(__float_as_uint(y)));
    return r;
}
__device__ __forceinline__ unsigned long long h2_to_f32x2(half2 h) {
    float2 f = __half22float2(h);
    return pack2(f.x, f.y);
}

__global__ __launch_bounds__(256, 3) void edge_kernel(
    const float* __restrict__ e, const int* __restrict__ eidx,
    const int* __restrict__ batch,
    const float* __restrict__ W0, const float* __restrict__ W1,
    const float* __restrict__ b1,
    float* __restrict__ out_bonds, float* __restrict__ out_coords,
    int N, int E, int edgeBlocks)
{
    if ((int)blockIdx.x >= edgeBlocks) {
        int idx = (blockIdx.x - edgeBlocks) * 256 + threadIdx.x;
        if (idx < N * 3) {
            int n = idx / 3, d = idx % 3;
            int b = batch[n];
            float m = g_sums[b * 3 + d] / fmaxf(g_cnt[b], 1.0f);
            out_coords[idx] = g_raw[idx] - m;
        }
        return;
    }

    extern __shared__ float sm[];
    half2* sWh  = (half2*)sm;                  // [34][128] col-pairs (0-31 WbW0, 32 w0d, 33 0)
    half2* sW1h = (half2*)(sm + 4352);         // [5][128]
    float* scv  = sm + 4352 + 640;             // [256]
    float* sg   = scv + 256;                   // [128][GPITCH]
    int*   sI   = (int*)(sg + 128 * GPITCH);
    int*   sJ   = sI + 128;
    int*   sK1  = sJ + 128;
    int*   sK2  = sK1 + 128;

    int tid = threadIdx.x, lane = tid & 31, wp = tid >> 5;
    int e0 = blockIdx.x * ETILE;

    for (int idx = tid; idx < QROWS * 128; idx += 256) {
        int q = idx >> 7, p = idx & 127;
        half2 hv;
        if (q < 32) {
            float2 w = *(const float2*)&g_wbw0[q * 256 + 2 * p];
            hv = __floats2half2_rn(w.x, w.y);
        } else if (q == 32) {
            hv = __floats2half2_rn(W0[256 * 256 + 2 * p], W0[256 * 256 + 2 * p + 1]);
        } else {
            hv = __floats2half2_rn(0.0f, 0.0f);
        }
        sWh[idx] = hv;
    }
    for (int idx = tid; idx < 5 * 128; idx += 256) {
        int b = idx >> 7, p = idx & 127;
        sW1h[idx] = __floats2half2_rn(W1[(2 * p) * NBT + b], W1[(2 * p + 1) * NBT + b]);
    }
    if (tid < 256) scv[tid] = g_cvec[tid];

    if (tid < ETILE) {
        int eg = e0 + tid;
        int i = 0, j = 0, k1 = -1, k2 = -1;
        float dval = 0.0f;
        if (eg < E) {
            j = eidx[eg];
            i = eidx[E + eg];
            k1 = g_map[j * N + i];
            k2 = g_map[i * N + j];
            int bi = batch[i], bj = batch[j];
            float inv_i = 1.0f / fmaxf(g_cnt[bi], 1.0f);
            float inv_j = 1.0f / fmaxf(g_cnt[bj], 1.0f);
            float dx = (g_raw[i*3+0] - g_sums[bi*3+0]*inv_i)
                     - (g_raw[j*3+0] - g_sums[bj*3+0]*inv_j);
            float dy = (g_raw[i*3+1] - g_sums[bi*3+1]*inv_i)
                     - (g_raw[j*3+1] - g_sums[bj*3+1]*inv_j);
            float dz = (g_raw[i*3+2] - g_sums[bi*3+2]*inv_i)
                     - (g_raw[j*3+2] - g_sums[bj*3+2]*inv_j);
            dval = dx * dx + dy * dy + dz * dz;
        }
        sI[tid] = i; sJ[tid] = j; sK1[tid] = k1; sK2[tid] = k2;
        sg[tid * GPITCH + 32] = dval;
        sg[tid * GPITCH + 33] = 0.0f;
    }
    __syncthreads();

    for (int idx = tid; idx < ETILE * 32; idx += 256) {
        int el = idx >> 5, q = idx & 31;
        int k1 = sK1[el], k2 = sK2[el];
        float g1 = (k1 >= 0) ? e[(size_t)k1 * EDIM + q] : 0.0f;
        float g2 = (k2 >= 0) ? e[(size_t)k2 * EDIM + q] : 0.0f;
        sg[el * GPITCH + q] = 0.5f * (g1 + g2);
    }
    __syncthreads();

    // ---- each warp: 16 edges, 4 subpasses of 4 ----
    for (int sub = 0; sub < 4; sub++) {
        int base = wp * 16 + sub * 4;

        unsigned long long acc[4][4];
#pragma unroll
        for (int t = 0; t < 4; t++) {
            unsigned long long cv = *(const unsigned long long*)&scv[2 * lane + 64 * t];
#pragma unroll
            for (int v = 0; v < 4; v++) acc[t][v] = cv;
        }

#pragma unroll 1
        for (int qp = 0; qp < 17; qp++) {
            unsigned long long g0[4], g1[4];
#pragma unroll
            for (int v = 0; v < 4; v++) {
                float2 gp = *(const float2*)&sg[(base + v) * GPITCH + 2 * qp];
                g0[v] = dup_f32x2(gp.x);
                g1[v] = dup_f32x2(gp.y);
            }
#pragma unroll
            for (int t = 0; t < 4; t++) {
                unsigned long long w0f = h2_to_f32x2(sWh[(2 * qp) * 128 + lane + 32 * t]);
                unsigned long long w1f = h2_to_f32x2(sWh[(2 * qp + 1) * 128 + lane + 32 * t]);
#pragma unroll
                for (int v = 0; v < 4; v++) {
                    ffma2(acc[t][v], w0f, g0[v]);
                    ffma2(acc[t][v], w1f, g1[v]);
                }
            }
        }

        // ---- epilogue per edge (fp16 T gathers) ----
#pragma unroll
        for (int v = 0; v < 4; v++) {
            int el = base + v;
            int eg = e0 + el;
            const half2* Ti = (const half2*)(g_Th + (size_t)sI[el] * 256);
            const half2* Tj = (const half2*)(g_Th + (size_t)sJ[el] * 256);

            unsigned long long pbp[NBT];
#pragma unroll
            for (int b = 0; b < NBT; b++) pbp[b] = 0ull;

#pragma unroll
            for (int t = 0; t < 4; t++) {
                int p0 = lane + 32 * t;
                float2 a  = unpack2(acc[t][v]);
                float2 ti = __half22float2(Ti[p0]);
                float2 tj = __half22float2(Tj[p0]);
                float z0 = silu_t(a.x + ti.x + tj.x);
                float z1 = silu_t(a.y + ti.y + tj.y);
                unsigned long long zp = pack2(z0, z1);
#pragma unroll
                for (int b = 0; b < NBT; b++) {
                    unsigned long long w1p = h2_to_f32x2(sW1h[b * 128 + p0]);
                    ffma2(pbp[b], zp, w1p);
                }
            }
            float pb[NBT];
#pragma unroll
            for (int b = 0; b < NBT; b++) {
                float2 u = unpack2(pbp[b]);
                pb[b] = u.x + u.y;
            }
#pragma unroll
            for (int b = 0; b < NBT; b++) {
#pragma unroll
                for (int off = 16; off; off >>= 1)
                    pb[b] += __shfl_xor_sync(0xffffffffu, pb[b], off);
            }
            if (lane == 0 && eg < E) {
#pragma unroll
                for (int b = 0; b < NBT; b++)
                    out_bonds[(size_t)eg * NBT + b] = pb[b] + b1[b];
            }
        }
    }
}

// ---------------- launch ----------------
extern "C" void kernel_launch(void* const* d_in, const int* in_sizes, int n_in,
                              void* d_out, int out_size)
{
    const float* s     = (const float*)d_in[0];
    const float* v     = (const float*)d_in[1];
    const float* p     = (const float*)d_in[2];
    const float* e     = (const float*)d_in[3];
    const int*   batch = (const int*)d_in[4];
    const int*   eidx  = (const int*)d_in[5];
    const float* Ws = (const float*)d_in[6];
    const float* bs = (const float*)d_in[7];
    const float* Wc = (const float*)d_in[8];
    const float* Wa = (const float*)d_in[9];
    const float* ba = (const float*)d_in[10];
    const float* Wb = (const float*)d_in[11];
    const float* bb = (const float*)d_in[12];
    const float* W0 = (const float*)d_in[13];
    const float* b0 = (const float*)d_in[14];
    const float* W1 = (const float*)d_in[15];
    const float* b1 = (const float*)d_in[16];

    int N = in_sizes[0] / SDIM;
    int E = in_sizes[5] / 2;

    float* out        = (float*)d_out;
    float* out_coords = out;
    float* out_atoms  = out + (size_t)N * 3;
    float* out_bonds  = out_atoms + (size_t)N * NAF;

    cudaFuncSetAttribute(edge_kernel, cudaFuncAttributeMaxDynamicSharedMemorySize,
                         EDGE_SMEM_BYTES);

    int init_blocks = (N * N + 1023) / 1024;
    init_kernel<<<init_blocks, 1024>>>(N);

    int nodeBlocks = (N + 15) / 16;
    node_fold_kernel<<<nodeBlocks + EDIM + 1, 256>>>(
        s, Ws, bs, W0, Wa, ba, Wb, bb, b0, out_atoms, N, nodeBlocks);

    int scatBlocks = (E + 255) / 256;
    int coordBlocks = (N + 7) / 8;
    prep_kernel<<<scatBlocks + coordBlocks, 256>>>(
        eidx, v, p, Wc, batch, N, E, scatBlocks);

    int edgeBlocks = (E + ETILE - 1) / ETILE;
    int finBlocks  = (N * 3 + 255) / 256;
    edge_kernel<<<edgeBlocks + finBlocks, 256, EDGE_SMEM_BYTES>>>(
        e, eidx, batch, W0, W1, b1, out_bonds, out_coords, N, E, edgeBlocks);
}

// round 14
// speedup vs baseline: 1.0601x; 1.0034x over previous
#include <cuda_runtime.h>
#include <cuda_bf16.h>
#include <cuda_fp16.h>
#include <cstdint>

#define SDIM 256
#define EDIM 32
#define VDIM 64
#define NMOL 64
#define NAF  16
#define NBT  5
#define MAXN 2048
#define ETILE 256
#define QROWS 34
#define GPITCH 34

// ---------------- device scratch (zero-initialized at load) ----------------
__device__ __half g_Th[MAXN * SDIM];       // T = s_h @ W0' in fp16
__device__ float  g_raw[MAXN * 3];
__device__ float  g_sums[NMOL * 3];
__device__ float  g_cnt[NMOL];
__device__ int    g_map[MAXN * MAXN];      // stores k+1 ; 0 = empty (self-cleaned)
__device__ float  g_wbw0[EDIM * SDIM];     // Wb @ W0'
__device__ float  g_cvec[SDIM];            // bb @ W0' + b0

__device__ __forceinline__ float silu_f(float x) {
    return __fdividef(x, 1.0f + __expf(-x));
}
__device__ __forceinline__ float silu_t(float x) {
    float h = 0.5f * x;
    float t;
    asm("tanh.approx.f32 %0, %1;" : "=f"(t) : "f"(h));
    return fmaf(h, t, h);
}

// ---------------- k0: fused node work (+foldw tail blocks, zeroes sums) ----------------
__global__ __launch_bounds__(256) void node_fold_kernel(
    const float* __restrict__ s, const float* __restrict__ Ws,
    const float* __restrict__ bs, const float* __restrict__ W0,
    const float* __restrict__ Wa, const float* __restrict__ ba,
    const float* __restrict__ Wb, const float* __restrict__ bb,
    const float* __restrict__ b0,
    float* __restrict__ out_atoms, int N, int nodeBlocks)
{
    if (blockIdx.x >= nodeBlocks) {
        int c = threadIdx.x;
        int r = blockIdx.x - nodeBlocks;
        if (r == EDIM) {
            // this block also zeroes the per-mol accumulators (exactly 256 words)
            if (c < NMOL * 3) g_sums[c] = 0.0f;
            else              g_cnt[c - NMOL * 3] = 0.0f;
        }
        const float* xrow = (r < EDIM) ? (Wb + r * SDIM) : bb;
        float a0 = 0, a1 = 0, a2 = 0, a3 = 0, a4 = 0, a5 = 0, a6 = 0, a7 = 0;
        for (int m = 0; m < SDIM; m += 8) {
            float x0 = xrow[m+0], x1 = xrow[m+1], x2 = xrow[m+2], x3 = xrow[m+3];
            float x4 = xrow[m+4], x5 = xrow[m+5], x6 = xrow[m+6], x7 = xrow[m+7];
            a0 += x0 * W0[(m+0)*SDIM+c]; a1 += x1 * W0[(m+1)*SDIM+c];
            a2 += x2 * W0[(m+2)*SDIM+c]; a3 += x3 * W0[(m+3)*SDIM+c];
            a4 += x4 * W0[(m+4)*SDIM+c]; a5 += x5 * W0[(m+5)*SDIM+c];
            a6 += x6 * W0[(m+6)*SDIM+c]; a7 += x7 * W0[(m+7)*SDIM+c];
        }
        float acc = ((a0+a1)+(a2+a3)) + ((a4+a5)+(a6+a7));
        if (r < EDIM) g_wbw0[r * SDIM + c] = acc;
        else          g_cvec[c] = acc + b0[c];
        return;
    }

    __shared__ float sX[16 * 256];
    __shared__ float sW[32 * 256];
    int tid = threadIdx.x, lane = tid & 31, wp = tid >> 5;
    int row0 = blockIdx.x * 16;

    for (int idx = tid; idx < 16 * 256; idx += 256) {
        int g = row0 * 256 + idx;
        sX[idx] = (g < N * 256) ? s[g] : 0.0f;
    }

    float acc[8][2];
#pragma unroll
    for (int u = 0; u < 8; u++) {
        float b = bs[lane + 32 * u];
        acc[u][0] = b; acc[u][1] = b;
    }
    for (int kc = 0; kc < 8; kc++) {
        __syncthreads();
        for (int idx = tid; idx < 8192; idx += 256)
            sW[idx] = Ws[kc * 32 * 256 + idx];
        __syncthreads();
#pragma unroll
        for (int kk = 0; kk < 32; kk++) {
            float w[8];
#pragma unroll
            for (int u = 0; u < 8; u++) w[u] = sW[kk * 256 + lane + 32 * u];
            float x0 = sX[(wp * 2 + 0) * 256 + kc * 32 + kk];
            float x1 = sX[(wp * 2 + 1) * 256 + kc * 32 + kk];
#pragma unroll
            for (int u = 0; u < 8; u++) {
                acc[u][0] += w[u] * x0;
                acc[u][1] += w[u] * x1;
            }
        }
    }
    __syncthreads();
#pragma unroll
    for (int v = 0; v < 2; v++) {
#pragma unroll
        for (int u = 0; u < 8; u++) {
            float z = silu_f(acc[u][v]);
            sX[(wp * 2 + v) * 256 + lane + 32 * u] = z;
        }
    }

#pragma unroll
    for (int u = 0; u < 8; u++) { acc[u][0] = 0.0f; acc[u][1] = 0.0f; }
    for (int kc = 0; kc < 8; kc++) {
        __syncthreads();
        for (int idx = tid; idx < 8192; idx += 256)
            sW[idx] = W0[kc * 32 * 256 + idx];
        __syncthreads();
#pragma unroll
        for (int kk = 0; kk < 32; kk++) {
            float w[8];
#pragma unroll
            for (int u = 0; u < 8; u++) w[u] = sW[kk * 256 + lane + 32 * u];
            float x0 = sX[(wp * 2 + 0) * 256 + kc * 32 + kk];
            float x1 = sX[(wp * 2 + 1) * 256 + kc * 32 + kk];
#pragma unroll
            for (int u = 0; u < 8; u++) {
                acc[u][0] += w[u] * x0;
                acc[u][1] += w[u] * x1;
            }
        }
    }
#pragma unroll
    for (int v = 0; v < 2; v++) {
        int r = row0 + wp * 2 + v;
        if (r < N) {
#pragma unroll
            for (int u = 0; u < 8; u++)
                g_Th[r * 256 + lane + 32 * u] = __float2half_rn(acc[u][v]);
        }
    }

    __syncthreads();
    for (int idx = tid; idx < SDIM * NAF; idx += 256) sW[idx] = Wa[idx];
    __syncthreads();
#pragma unroll
    for (int v = 0; v < 2; v++) {
        int rl = wp * 2 + v;
        int r = row0 + rl;
        float a[NAF];
#pragma unroll
        for (int q = 0; q < NAF; q++) a[q] = 0.0f;
#pragma unroll
        for (int m = 0; m < 8; m++) {
            int c = lane + 32 * m;
            float x = sX[rl * 256 + c];
#pragma unroll
            for (int q = 0; q < NAF; q++) a[q] += x * sW[c * NAF + q];
        }
#pragma unroll
        for (int q = 0; q < NAF; q++) {
#pragma unroll
            for (int off = 16; off; off >>= 1)
                a[q] += __shfl_xor_sync(0xffffffffu, a[q], off);
        }
        if (r < N && lane < NAF)
            out_atoms[(size_t)r * NAF + lane] = a[lane] + ba[lane];
    }
}

// ---------------- k1: scatter (k+1 encoding) ----------------
__global__ void scatter_kernel(const int* __restrict__ eidx, int N, int E)
{
    int k = blockIdx.x * blockDim.x + threadIdx.x;
    if (k >= E) return;
    int j = eidx[k];
    int i = eidx[E + k];
    atomicMax(&g_map[j * N + i], k + 1);
}

// ---------------- k2: coords sums ----------------
__global__ void coords_kernel(const float* __restrict__ v, const float* __restrict__ p,
                              const float* __restrict__ Wc, const int* __restrict__ batch,
                              int N)
{
    int n = blockIdx.x * 8 + (threadIdx.x >> 5);
    int lane = threadIdx.x & 31;
    if (n >= N) return;
    const float* vb = v + (size_t)n * 3 * VDIM;
    float w0 = Wc[lane], w1 = Wc[32 + lane];
    float a0 = vb[lane] * w0 + vb[32 + lane] * w1;
    float a1 = vb[64 + lane] * w0 + vb[96 + lane] * w1;
    float a2 = vb[128 + lane] * w0 + vb[160 + lane] * w1;
#pragma unroll
    for (int off = 16; off; off >>= 1) {
        a0 += __shfl_xor_sync(0xffffffffu, a0, off);
        a1 += __shfl_xor_sync(0xffffffffu, a1, off);
        a2 += __shfl_xor_sync(0xffffffffu, a2, off);
    }
    if (lane == 0) {
        int b = batch[n];
        float r0 = p[n * 3 + 0] + a0;
        float r1 = p[n * 3 + 1] + a1;
        float r2 = p[n * 3 + 2] + a2;
        g_raw[n * 3 + 0] = r0; g_raw[n * 3 + 1] = r1; g_raw[n * 3 + 2] = r2;
        atomicAdd(&g_sums[b * 3 + 0], r0);
        atomicAdd(&g_sums[b * 3 + 1], r1);
        atomicAdd(&g_sums[b * 3 + 2], r2);
        atomicAdd(&g_cnt[b], 1.0f);
    }
}

// ---------------- k3 (PROFILED): fused edge network + coords-finalize tail ----------------
// smem u32 slots: sWh 4352 | sW1h 640 | scv 256 | sg 256*34=8704 | ints 1024
#define EDGE_SMEM_BYTES ((4352 + 640 + 256 + 8704 + 1024) * 4)

__device__ __forceinline__ unsigned long long dup_f32x2(float x) {
    unsigned long long r;
    asm("mov.b64 %0, {%1, %1};" : "=l"(r) : "r"(__float_as_uint(x)));
    return r;
}
__device__ __forceinline__ void ffma2(unsigned long long& acc,
                                      unsigned long long a, unsigned long long b) {
    asm("fma.rn.f32x2 %0, %1, %2, %0;" : "+l"(acc) : "l"(a), "l"(b));
}
__device__ __forceinline__ float2 unpack2(unsigned long long x) {
    float2 r;
    asm("mov.b64 {%0, %1}, %2;" : "=f"(r.x), "=f"(r.y) : "l"(x));
    return r;
}
__device__ __forceinline__ unsigned long long pack2(float x, float y) {
    unsigned long long r;
    asm("mov.b64 %0, {%1, %2};" : "=l"(r) : "r"(__float_as_uint(x)), "r"(__float_as_uint(y)));
    return r;
}
__device__ __forceinline__ unsigned long long h2_to_f32x2(half2 h) {
    float2 f = __half22float2(h);
    return pack2(f.x, f.y);
}

__global__ __launch_bounds__(256, 3) void edge_kernel(
    const float* __restrict__ e, const int* __restrict__ eidx,
    const int* __restrict__ batch,
    const float* __restrict__ W0, const float* __restrict__ W1,
    const float* __restrict__ b1,
    float* __restrict__ out_bonds, float* __restrict__ out_coords,
    int N, int E, int edgeBlocks)
{
    if ((int)blockIdx.x >= edgeBlocks) {
        int idx = (blockIdx.x - edgeBlocks) * 256 + threadIdx.x;
        if (idx < N * 3) {
            int n = idx / 3, d = idx % 3;
            int b = batch[n];
            float m = g_sums[b * 3 + d] / fmaxf(g_cnt[b], 1.0f);
            out_coords[idx] = g_raw[idx] - m;
        }
        return;
    }

    extern __shared__ float sm[];
    half2* sWh  = (half2*)sm;                  // [34][128] (0-31 WbW0, 32 w0d, 33 0)
    half2* sW1h = (half2*)(sm + 4352);         // [5][128]
    float* scv  = sm + 4352 + 640;             // [256]
    float* sg   = scv + 256;                   // [256][GPITCH]
    int*   sI   = (int*)(sg + ETILE * GPITCH);
    int*   sJ   = sI + ETILE;
    int*   sK1  = sJ + ETILE;
    int*   sK2  = sK1 + ETILE;

    int tid = threadIdx.x, lane = tid & 31, wp = tid >> 5;
    int e0 = blockIdx.x * ETILE;

    for (int idx = tid; idx < QROWS * 128; idx += 256) {
        int q = idx >> 7, p = idx & 127;
        half2 hv;
        if (q < 32) {
            float2 w = *(const float2*)&g_wbw0[q * 256 + 2 * p];
            hv = __floats2half2_rn(w.x, w.y);
        } else if (q == 32) {
            hv = __floats2half2_rn(W0[256 * 256 + 2 * p], W0[256 * 256 + 2 * p + 1]);
        } else {
            hv = __floats2half2_rn(0.0f, 0.0f);
        }
        sWh[idx] = hv;
    }
    for (int idx = tid; idx < 5 * 128; idx += 256) {
        int b = idx >> 7, p = idx & 127;
        sW1h[idx] = __floats2half2_rn(W1[(2 * p) * NBT + b], W1[(2 * p + 1) * NBT + b]);
    }
    if (tid < 256) scv[tid] = g_cvec[tid];

    // per-edge meta (one edge per thread; k+1 decode)
    {
        int eg = e0 + tid;
        int i = 0, j = 0, k1 = -1, k2 = -1;
        float dval = 0.0f;
        if (eg < E) {
            j = eidx[eg];
            i = eidx[E + eg];
            k1 = g_map[j * N + i] - 1;
            k2 = g_map[i * N + j] - 1;
            int bi = batch[i], bj = batch[j];
            float inv_i = 1.0f / fmaxf(g_cnt[bi], 1.0f);
            float inv_j = 1.0f / fmaxf(g_cnt[bj], 1.0f);
            float dx = (g_raw[i*3+0] - g_sums[bi*3+0]*inv_i)
                     - (g_raw[j*3+0] - g_sums[bj*3+0]*inv_j);
            float dy = (g_raw[i*3+1] - g_sums[bi*3+1]*inv_i)
                     - (g_raw[j*3+1] - g_sums[bj*3+1]*inv_j);
            float dz = (g_raw[i*3+2] - g_sums[bi*3+2]*inv_i)
                     - (g_raw[j*3+2] - g_sums[bj*3+2]*inv_j);
            dval = dx * dx + dy * dy + dz * dz;
        }
        sI[tid] = i; sJ[tid] = j; sK1[tid] = k1; sK2[tid] = k2;
        sg[tid * GPITCH + 32] = dval;
        sg[tid * GPITCH + 33] = 0.0f;
    }
    __syncthreads();

    for (int idx = tid; idx < ETILE * 32; idx += 256) {
        int el = idx >> 5, q = idx & 31;
        int k1 = sK1[el], k2 = sK2[el];
        float g1 = (k1 >= 0) ? e[(size_t)k1 * EDIM + q] : 0.0f;
        float g2 = (k2 >= 0) ? e[(size_t)k2 * EDIM + q] : 0.0f;
        sg[el * GPITCH + q] = 0.5f * (g1 + g2);
    }
    __syncthreads();

    // ---- each warp: 32 edges, 8 subpasses of 4 ----
    for (int sub = 0; sub < 8; sub++) {
        int base = wp * 32 + sub * 4;

        unsigned long long acc[4][4];
#pragma unroll
        for (int t = 0; t < 4; t++) {
            unsigned long long cv = *(const unsigned long long*)&scv[2 * lane + 64 * t];
#pragma unroll
            for (int v = 0; v < 4; v++) acc[t][v] = cv;
        }

#pragma unroll 1
        for (int qp = 0; qp < 17; qp++) {
            unsigned long long g0[4], g1[4];
#pragma unroll
            for (int v = 0; v < 4; v++) {
                float2 gp = *(const float2*)&sg[(base + v) * GPITCH + 2 * qp];
                g0[v] = dup_f32x2(gp.x);
                g1[v] = dup_f32x2(gp.y);
            }
#pragma unroll
            for (int t = 0; t < 4; t++) {
                unsigned long long w0f = h2_to_f32x2(sWh[(2 * qp) * 128 + lane + 32 * t]);
                unsigned long long w1f = h2_to_f32x2(sWh[(2 * qp + 1) * 128 + lane + 32 * t]);
#pragma unroll
                for (int v = 0; v < 4; v++) {
                    ffma2(acc[t][v], w0f, g0[v]);
                    ffma2(acc[t][v], w1f, g1[v]);
                }
            }
        }

        // ---- epilogue per edge (fp16 T gathers) ----
#pragma unroll
        for (int v = 0; v < 4; v++) {
            int el = base + v;
            int eg = e0 + el;
            const half2* Ti = (const half2*)(g_Th + (size_t)sI[el] * 256);
            const half2* Tj = (const half2*)(g_Th + (size_t)sJ[el] * 256);

            unsigned long long pbp[NBT];
#pragma unroll
            for (int b = 0; b < NBT; b++) pbp[b] = 0ull;

#pragma unroll
            for (int t = 0; t < 4; t++) {
                int p0 = lane + 32 * t;
                float2 a  = unpack2(acc[t][v]);
                float2 ti = __half22float2(Ti[p0]);
                float2 tj = __half22float2(Tj[p0]);
                float z0 = silu_t(a.x + ti.x + tj.x);
                float z1 = silu_t(a.y + ti.y + tj.y);
                unsigned long long zp = pack2(z0, z1);
#pragma unroll
                for (int b = 0; b < NBT; b++) {
                    unsigned long long w1p = h2_to_f32x2(sW1h[b * 128 + p0]);
                    ffma2(pbp[b], zp, w1p);
                }
            }
            float pb[NBT];
#pragma unroll
            for (int b = 0; b < NBT; b++) {
                float2 u = unpack2(pbp[b]);
                pb[b] = u.x + u.y;
            }
#pragma unroll
            for (int b = 0; b < NBT; b++) {
#pragma unroll
                for (int off = 16; off; off >>= 1)
                    pb[b] += __shfl_xor_sync(0xffffffffu, pb[b], off);
            }
            if (lane == 0 && eg < E) {
#pragma unroll
                for (int b = 0; b < NBT; b++)
                    out_bonds[(size_t)eg * NBT + b] = pb[b] + b1[b];
            }
        }
    }
}

// ---------------- k4: self-clean g_map (restores zero state for next replay) ----------------
__global__ void cleanup_kernel(const int* __restrict__ eidx, int N, int E)
{
    int k = blockIdx.x * blockDim.x + threadIdx.x;
    if (k >= E) return;
    int j = eidx[k];
    int i = eidx[E + k];
    g_map[j * N + i] = 0;
}

// ---------------- launch ----------------
extern "C" void kernel_launch(void* const* d_in, const int* in_sizes, int n_in,
                              void* d_out, int out_size)
{
    const float* s     = (const float*)d_in[0];
    const float* v     = (const float*)d_in[1];
    const float* p     = (const float*)d_in[2];
    const float* e     = (const float*)d_in[3];
    const int*   batch = (const int*)d_in[4];
    const int*   eidx  = (const int*)d_in[5];
    const float* Ws = (const float*)d_in[6];
    const float* bs = (const float*)d_in[7];
    const float* Wc = (const float*)d_in[8];
    const float* Wa = (const float*)d_in[9];
    const float* ba = (const float*)d_in[10];
    const float* Wb = (const float*)d_in[11];
    const float* bb = (const float*)d_in[12];
    const float* W0 = (const float*)d_in[13];
    const float* b0 = (const float*)d_in[14];
    const float* W1 = (const float*)d_in[15];
    const float* b1 = (const float*)d_in[16];

    int N = in_sizes[0] / SDIM;
    int E = in_sizes[5] / 2;

    float* out        = (float*)d_out;
    float* out_coords = out;
    float* out_atoms  = out + (size_t)N * 3;
    float* out_bonds  = out_atoms + (size_t)N * NAF;

    cudaFuncSetAttribute(edge_kernel, cudaFuncAttributeMaxDynamicSharedMemorySize,
                         EDGE_SMEM_BYTES);

    // launch 0: node GEMMs + atoms + foldw + sums-zeroing
    int nodeBlocks = (N + 15) / 16;
    node_fold_kernel<<<nodeBlocks + EDIM + 1, 256>>>(
        s, Ws, bs, W0, Wa, ba, Wb, bb, b0, out_atoms, N, nodeBlocks);

    // launch 1: scatter (k+1)
    scatter_kernel<<<(E + 255) / 256, 256>>>(eidx, N, E);

    // launch 2: coords sums
    coords_kernel<<<(N + 7) / 8, 256>>>(v, p, Wc, batch, N);

    // launch 3 (PROFILED): fused edge network + coords finalize
    int edgeBlocks = (E + ETILE - 1) / ETILE;
    int finBlocks  = (N * 3 + 255) / 256;
    edge_kernel<<<edgeBlocks + finBlocks, 256, EDGE_SMEM_BYTES>>>(
        e, eidx, batch, W0, W1, b1, out_bonds, out_coords, N, E, edgeBlocks);

    // launch 4: self-clean g_map for graph replay
    cleanup_kernel<<<(E + 255) / 256, 256>>>(eidx, N, E);
}

// round 15
// speedup vs baseline: 1.0934x; 1.0314x over previous
#include <cuda_runtime.h>
#include <cuda_bf16.h>
#include <cuda_fp16.h>
#include <cstdint>

#define SDIM 256
#define EDIM 32
#define VDIM 64
#define NMOL 64
#define NAF  16
#define NBT  5
#define MAXN 2048
#define ETILE 256
#define QROWS 34
#define GPITCH 34

// ---------------- device scratch (zero-initialized at load; self-cleaned per call) ----------------
__device__ __half g_Th[MAXN * SDIM];       // T = s_h @ W0' in fp16
__device__ float  g_raw[MAXN * 3];
__device__ float  g_sums[NMOL * 3];        // zeroed by cleanup (and at load)
__device__ float  g_cnt[NMOL];             // zeroed by cleanup (and at load)
__device__ int    g_map[MAXN * MAXN];      // stores k+1 ; 0 = empty (self-cleaned)
__device__ float  g_wbw0[EDIM * SDIM];     // Wb @ W0'
__device__ float  g_cvec[SDIM];            // bb @ W0' + b0

__device__ __forceinline__ float silu_f(float x) {
    return __fdividef(x, 1.0f + __expf(-x));
}
__device__ __forceinline__ float silu_t(float x) {
    float h = 0.5f * x;
    float t;
    asm("tanh.approx.f32 %0, %1;" : "=f"(t) : "f"(h));
    return fmaf(h, t, h);
}

// ---------------- k0: MEGA prologue: node GEMMs+atoms | foldw | scatter | coords ----------------
// block ranges: [0,nodeBlocks) node ; [nodeBlocks, +33) foldw ; then scatter ; then coords.
// All four phases are mutually independent (no intra-launch ordering needed):
//   node  writes g_Th, out_atoms          (reads s,Ws,bs,W0,Wa,ba)
//   foldw writes g_wbw0, g_cvec           (reads Wb,bb,W0,b0)
//   scat  writes g_map (atomicMax, k+1)   (reads eidx)
//   coord writes g_raw, g_sums, g_cnt (+) (reads v,p,Wc,batch; sums pre-zeroed by cleanup/load)
__global__ __launch_bounds__(256) void mega_kernel(
    const float* __restrict__ s, const float* __restrict__ Ws,
    const float* __restrict__ bs, const float* __restrict__ W0,
    const float* __restrict__ Wa, const float* __restrict__ ba,
    const float* __restrict__ Wb, const float* __restrict__ bb,
    const float* __restrict__ b0,
    const int* __restrict__ eidx,
    const float* __restrict__ v, const float* __restrict__ p,
    const float* __restrict__ Wc, const int* __restrict__ batch,
    float* __restrict__ out_atoms,
    int N, int E, int nodeBlocks, int scatBlocks)
{
    int bid = blockIdx.x;
    int tid = threadIdx.x;

    // ---- phase: foldw ----
    if (bid >= nodeBlocks && bid < nodeBlocks + EDIM + 1) {
        int c = tid;
        int r = bid - nodeBlocks;
        const float* xrow = (r < EDIM) ? (Wb + r * SDIM) : bb;
        float a0 = 0, a1 = 0, a2 = 0, a3 = 0, a4 = 0, a5 = 0, a6 = 0, a7 = 0;
        for (int m = 0; m < SDIM; m += 8) {
            float x0 = xrow[m+0], x1 = xrow[m+1], x2 = xrow[m+2], x3 = xrow[m+3];
            float x4 = xrow[m+4], x5 = xrow[m+5], x6 = xrow[m+6], x7 = xrow[m+7];
            a0 += x0 * W0[(m+0)*SDIM+c]; a1 += x1 * W0[(m+1)*SDIM+c];
            a2 += x2 * W0[(m+2)*SDIM+c]; a3 += x3 * W0[(m+3)*SDIM+c];
            a4 += x4 * W0[(m+4)*SDIM+c]; a5 += x5 * W0[(m+5)*SDIM+c];
            a6 += x6 * W0[(m+6)*SDIM+c]; a7 += x7 * W0[(m+7)*SDIM+c];
        }
        float acc = ((a0+a1)+(a2+a3)) + ((a4+a5)+(a6+a7));
        if (r < EDIM) g_wbw0[r * SDIM + c] = acc;
        else          g_cvec[c] = acc + b0[c];
        return;
    }

    // ---- phase: scatter ----
    if (bid >= nodeBlocks + EDIM + 1 && bid < nodeBlocks + EDIM + 1 + scatBlocks) {
        int k = (bid - (nodeBlocks + EDIM + 1)) * 256 + tid;
        if (k < E) {
            int j = eidx[k];
            int i = eidx[E + k];
            atomicMax(&g_map[j * N + i], k + 1);
        }
        return;
    }

    // ---- phase: coords ----
    if (bid >= nodeBlocks + EDIM + 1 + scatBlocks) {
        int n = (bid - (nodeBlocks + EDIM + 1 + scatBlocks)) * 8 + (tid >> 5);
        int lane = tid & 31;
        if (n >= N) return;
        const float* vb = v + (size_t)n * 3 * VDIM;
        float w0 = Wc[lane], w1 = Wc[32 + lane];
        float a0 = vb[lane] * w0 + vb[32 + lane] * w1;
        float a1 = vb[64 + lane] * w0 + vb[96 + lane] * w1;
        float a2 = vb[128 + lane] * w0 + vb[160 + lane] * w1;
#pragma unroll
        for (int off = 16; off; off >>= 1) {
            a0 += __shfl_xor_sync(0xffffffffu, a0, off);
            a1 += __shfl_xor_sync(0xffffffffu, a1, off);
            a2 += __shfl_xor_sync(0xffffffffu, a2, off);
        }
        if (lane == 0) {
            int b = batch[n];
            float r0 = p[n * 3 + 0] + a0;
            float r1 = p[n * 3 + 1] + a1;
            float r2 = p[n * 3 + 2] + a2;
            g_raw[n * 3 + 0] = r0; g_raw[n * 3 + 1] = r1; g_raw[n * 3 + 2] = r2;
            atomicAdd(&g_sums[b * 3 + 0], r0);
            atomicAdd(&g_sums[b * 3 + 1], r1);
            atomicAdd(&g_sums[b * 3 + 2], r2);
            atomicAdd(&g_cnt[b], 1.0f);
        }
        return;
    }

    // ---- phase: node GEMMs + atoms ----
    __shared__ float sX[16 * 256];
    __shared__ float sW[32 * 256];
    int lane = tid & 31, wp = tid >> 5;
    int row0 = bid * 16;

    for (int idx = tid; idx < 16 * 256; idx += 256) {
        int g = row0 * 256 + idx;
        sX[idx] = (g < N * 256) ? s[g] : 0.0f;
    }

    float acc[8][2];
#pragma unroll
    for (int u = 0; u < 8; u++) {
        float b = bs[lane + 32 * u];
        acc[u][0] = b; acc[u][1] = b;
    }
    for (int kc = 0; kc < 8; kc++) {
        __syncthreads();
        for (int idx = tid; idx < 8192; idx += 256)
            sW[idx] = Ws[kc * 32 * 256 + idx];
        __syncthreads();
#pragma unroll
        for (int kk = 0; kk < 32; kk++) {
            float w[8];
#pragma unroll
            for (int u = 0; u < 8; u++) w[u] = sW[kk * 256 + lane + 32 * u];
            float x0 = sX[(wp * 2 + 0) * 256 + kc * 32 + kk];
            float x1 = sX[(wp * 2 + 1) * 256 + kc * 32 + kk];
#pragma unroll
            for (int u = 0; u < 8; u++) {
                acc[u][0] += w[u] * x0;
                acc[u][1] += w[u] * x1;
            }
        }
    }
    __syncthreads();
#pragma unroll
    for (int v2 = 0; v2 < 2; v2++) {
#pragma unroll
        for (int u = 0; u < 8; u++) {
            float z = silu_f(acc[u][v2]);
            sX[(wp * 2 + v2) * 256 + lane + 32 * u] = z;
        }
    }

#pragma unroll
    for (int u = 0; u < 8; u++) { acc[u][0] = 0.0f; acc[u][1] = 0.0f; }
    for (int kc = 0; kc < 8; kc++) {
        __syncthreads();
        for (int idx = tid; idx < 8192; idx += 256)
            sW[idx] = W0[kc * 32 * 256 + idx];
        __syncthreads();
#pragma unroll
        for (int kk = 0; kk < 32; kk++) {
            float w[8];
#pragma unroll
            for (int u = 0; u < 8; u++) w[u] = sW[kk * 256 + lane + 32 * u];
            float x0 = sX[(wp * 2 + 0) * 256 + kc * 32 + kk];
            float x1 = sX[(wp * 2 + 1) * 256 + kc * 32 + kk];
#pragma unroll
            for (int u = 0; u < 8; u++) {
                acc[u][0] += w[u] * x0;
                acc[u][1] += w[u] * x1;
            }
        }
    }
#pragma unroll
    for (int v2 = 0; v2 < 2; v2++) {
        int r = row0 + wp * 2 + v2;
        if (r < N) {
#pragma unroll
            for (int u = 0; u < 8; u++)
                g_Th[r * 256 + lane + 32 * u] = __float2half_rn(acc[u][v2]);
        }
    }

    __syncthreads();
    for (int idx = tid; idx < SDIM * NAF; idx += 256) sW[idx] = Wa[idx];
    __syncthreads();
#pragma unroll
    for (int v2 = 0; v2 < 2; v2++) {
        int rl = wp * 2 + v2;
        int r = row0 + rl;
        float a[NAF];
#pragma unroll
        for (int q = 0; q < NAF; q++) a[q] = 0.0f;
#pragma unroll
        for (int m = 0; m < 8; m++) {
            int c = lane + 32 * m;
            float x = sX[rl * 256 + c];
#pragma unroll
            for (int q = 0; q < NAF; q++) a[q] += x * sW[c * NAF + q];
        }
#pragma unroll
        for (int q = 0; q < NAF; q++) {
#pragma unroll
            for (int off = 16; off; off >>= 1)
                a[q] += __shfl_xor_sync(0xffffffffu, a[q], off);
        }
        if (r < N && lane < NAF)
            out_atoms[(size_t)r * NAF + lane] = a[lane] + ba[lane];
    }
}

// ---------------- k1: fused edge network + coords-finalize tail ----------------
#define EDGE_SMEM_BYTES ((4352 + 640 + 256 + 8704 + 1024) * 4)

__device__ __forceinline__ unsigned long long dup_f32x2(float x) {
    unsigned long long r;
    asm("mov.b64 %0, {%1, %1};" : "=l"(r) : "r"(__float_as_uint(x)));
    return r;
}
__device__ __forceinline__ void ffma2(unsigned long long& acc,
                                      unsigned long long a, unsigned long long b) {
    asm("fma.rn.f32x2 %0, %1, %2, %0;" : "+l"(acc) : "l"(a), "l"(b));
}
__device__ __forceinline__ float2 unpack2(unsigned long long x) {
    float2 r;
    asm("mov.b64 {%0, %1}, %2;" : "=f"(r.x), "=f"(r.y) : "l"(x));
    return r;
}
__device__ __forceinline__ unsigned long long pack2(float x, float y) {
    unsigned long long r;
    asm("mov.b64 %0, {%1, %2};" : "=l"(r) : "r"(__float_as_uint(x)), "r"(__float_as_uint(y)));
    return r;
}
__device__ __forceinline__ unsigned long long h2_to_f32x2(half2 h) {
    float2 f = __half22float2(h);
    return pack2(f.x, f.y);
}

__global__ __launch_bounds__(256, 3) void edge_kernel(
    const float* __restrict__ e, const int* __restrict__ eidx,
    const int* __restrict__ batch,
    const float* __restrict__ W0, const float* __restrict__ W1,
    const float* __restrict__ b1,
    float* __restrict__ out_bonds, float* __restrict__ out_coords,
    int N, int E, int edgeBlocks)
{
    if ((int)blockIdx.x >= edgeBlocks) {
        int idx = (blockIdx.x - edgeBlocks) * 256 + threadIdx.x;
        if (idx < N * 3) {
            int n = idx / 3, d = idx % 3;
            int b = batch[n];
            float m = g_sums[b * 3 + d] / fmaxf(g_cnt[b], 1.0f);
            out_coords[idx] = g_raw[idx] - m;
        }
        return;
    }

    extern __shared__ float sm[];
    half2* sWh  = (half2*)sm;                  // [34][128] (0-31 WbW0, 32 w0d, 33 0)
    half2* sW1h = (half2*)(sm + 4352);         // [5][128]
    float* scv  = sm + 4352 + 640;             // [256]
    float* sg   = scv + 256;                   // [256][GPITCH]
    int*   sI   = (int*)(sg + ETILE * GPITCH);
    int*   sJ   = sI + ETILE;
    int*   sK1  = sJ + ETILE;
    int*   sK2  = sK1 + ETILE;

    int tid = threadIdx.x, lane = tid & 31, wp = tid >> 5;
    int e0 = blockIdx.x * ETILE;

    for (int idx = tid; idx < QROWS * 128; idx += 256) {
        int q = idx >> 7, p = idx & 127;
        half2 hv;
        if (q < 32) {
            float2 w = *(const float2*)&g_wbw0[q * 256 + 2 * p];
            hv = __floats2half2_rn(w.x, w.y);
        } else if (q == 32) {
            hv = __floats2half2_rn(W0[256 * 256 + 2 * p], W0[256 * 256 + 2 * p + 1]);
        } else {
            hv = __floats2half2_rn(0.0f, 0.0f);
        }
        sWh[idx] = hv;
    }
    for (int idx = tid; idx < 5 * 128; idx += 256) {
        int b = idx >> 7, p = idx & 127;
        sW1h[idx] = __floats2half2_rn(W1[(2 * p) * NBT + b], W1[(2 * p + 1) * NBT + b]);
    }
    if (tid < 256) scv[tid] = g_cvec[tid];

    {
        int eg = e0 + tid;
        int i = 0, j = 0, k1 = -1, k2 = -1;
        float dval = 0.0f;
        if (eg < E) {
            j = eidx[eg];
            i = eidx[E + eg];
            k1 = g_map[j * N + i] - 1;
            k2 = g_map[i * N + j] - 1;
            int bi = batch[i], bj = batch[j];
            float inv_i = 1.0f / fmaxf(g_cnt[bi], 1.0f);
            float inv_j = 1.0f / fmaxf(g_cnt[bj], 1.0f);
            float dx = (g_raw[i*3+0] - g_sums[bi*3+0]*inv_i)
                     - (g_raw[j*3+0] - g_sums[bj*3+0]*inv_j);
            float dy = (g_raw[i*3+1] - g_sums[bi*3+1]*inv_i)
                     - (g_raw[j*3+1] - g_sums[bj*3+1]*inv_j);
            float dz = (g_raw[i*3+2] - g_sums[bi*3+2]*inv_i)
                     - (g_raw[j*3+2] - g_sums[bj*3+2]*inv_j);
            dval = dx * dx + dy * dy + dz * dz;
        }
        sI[tid] = i; sJ[tid] = j; sK1[tid] = k1; sK2[tid] = k2;
        sg[tid * GPITCH + 32] = dval;
        sg[tid * GPITCH + 33] = 0.0f;
    }
    __syncthreads();

    for (int idx = tid; idx < ETILE * 32; idx += 256) {
        int el = idx >> 5, q = idx & 31;
        int k1 = sK1[el], k2 = sK2[el];
        float g1 = (k1 >= 0) ? e[(size_t)k1 * EDIM + q] : 0.0f;
        float g2 = (k2 >= 0) ? e[(size_t)k2 * EDIM + q] : 0.0f;
        sg[el * GPITCH + q] = 0.5f * (g1 + g2);
    }
    __syncthreads();

    for (int sub = 0; sub < 8; sub++) {
        int base = wp * 32 + sub * 4;

        unsigned long long acc[4][4];
#pragma unroll
        for (int t = 0; t < 4; t++) {
            unsigned long long cv = *(const unsigned long long*)&scv[2 * lane + 64 * t];
#pragma unroll
            for (int v = 0; v < 4; v++) acc[t][v] = cv;
        }

#pragma unroll 1
        for (int qp = 0; qp < 17; qp++) {
            unsigned long long g0[4], g1[4];
#pragma unroll
            for (int v = 0; v < 4; v++) {
                float2 gp = *(const float2*)&sg[(base + v) * GPITCH + 2 * qp];
                g0[v] = dup_f32x2(gp.x);
                g1[v] = dup_f32x2(gp.y);
            }
#pragma unroll
            for (int t = 0; t < 4; t++) {
                unsigned long long w0f = h2_to_f32x2(sWh[(2 * qp) * 128 + lane + 32 * t]);
                unsigned long long w1f = h2_to_f32x2(sWh[(2 * qp + 1) * 128 + lane + 32 * t]);
#pragma unroll
                for (int v = 0; v < 4; v++) {
                    ffma2(acc[t][v], w0f, g0[v]);
                    ffma2(acc[t][v], w1f, g1[v]);
                }
            }
        }

#pragma unroll
        for (int v = 0; v < 4; v++) {
            int el = base + v;
            int eg = e0 + el;
            const half2* Ti = (const half2*)(g_Th + (size_t)sI[el] * 256);
            const half2* Tj = (const half2*)(g_Th + (size_t)sJ[el] * 256);

            unsigned long long pbp[NBT];
#pragma unroll
            for (int b = 0; b < NBT; b++) pbp[b] = 0ull;

#pragma unroll
            for (int t = 0; t < 4; t++) {
                int p0 = lane + 32 * t;
                float2 a  = unpack2(acc[t][v]);
                float2 ti = __half22float2(Ti[p0]);
                float2 tj = __half22float2(Tj[p0]);
                float z0 = silu_t(a.x + ti.x + tj.x);
                float z1 = silu_t(a.y + ti.y + tj.y);
                unsigned long long zp = pack2(z0, z1);
#pragma unroll
                for (int b = 0; b < NBT; b++) {
                    unsigned long long w1p = h2_to_f32x2(sW1h[b * 128 + p0]);
                    ffma2(pbp[b], zp, w1p);
                }
            }
            float pb[NBT];
#pragma unroll
            for (int b = 0; b < NBT; b++) {
                float2 u = unpack2(pbp[b]);
                pb[b] = u.x + u.y;
            }
#pragma unroll
            for (int b = 0; b < NBT; b++) {
#pragma unroll
                for (int off = 16; off; off >>= 1)
                    pb[b] += __shfl_xor_sync(0xffffffffu, pb[b], off);
            }
            if (lane == 0 && eg < E) {
#pragma unroll
                for (int b = 0; b < NBT; b++)
                    out_bonds[(size_t)eg * NBT + b] = pb[b] + b1[b];
            }
        }
    }
}

// ---------------- k2: self-clean g_map + zero sums/cnt for next replay ----------------
__global__ void cleanup_kernel(const int* __restrict__ eidx, int N, int E)
{
    int k = blockIdx.x * blockDim.x + threadIdx.x;
    if (blockIdx.x == 0) {
        int c = threadIdx.x;
        if (c < NMOL * 3) g_sums[c] = 0.0f;
        else              g_cnt[c - NMOL * 3] = 0.0f;
    }
    if (k >= E) return;
    int j = eidx[k];
    int i = eidx[E + k];
    g_map[j * N + i] = 0;
}

// ---------------- launch ----------------
extern "C" void kernel_launch(void* const* d_in, const int* in_sizes, int n_in,
                              void* d_out, int out_size)
{
    const float* s     = (const float*)d_in[0];
    const float* v     = (const float*)d_in[1];
    const float* p     = (const float*)d_in[2];
    const float* e     = (const float*)d_in[3];
    const int*   batch = (const int*)d_in[4];
    const int*   eidx  = (const int*)d_in[5];
    const float* Ws = (const float*)d_in[6];
    const float* bs = (const float*)d_in[7];
    const float* Wc = (const float*)d_in[8];
    const float* Wa = (const float*)d_in[9];
    const float* ba = (const float*)d_in[10];
    const float* Wb = (const float*)d_in[11];
    const float* bb = (const float*)d_in[12];
    const float* W0 = (const float*)d_in[13];
    const float* b0 = (const float*)d_in[14];
    const float* W1 = (const float*)d_in[15];
    const float* b1 = (const float*)d_in[16];

    int N = in_sizes[0] / SDIM;
    int E = in_sizes[5] / 2;

    float* out        = (float*)d_out;
    float* out_coords = out;
    float* out_atoms  = out + (size_t)N * 3;
    float* out_bonds  = out_atoms + (size_t)N * NAF;

    cudaFuncSetAttribute(edge_kernel, cudaFuncAttributeMaxDynamicSharedMemorySize,
                         EDGE_SMEM_BYTES);

    // launch 0: MEGA prologue (node GEMMs + atoms | foldw | scatter | coords)
    int nodeBlocks  = (N + 15) / 16;
    int scatBlocks  = (E + 255) / 256;
    int coordBlocks = (N + 7) / 8;
    mega_kernel<<<nodeBlocks + EDIM + 1 + scatBlocks + coordBlocks, 256>>>(
        s, Ws, bs, W0, Wa, ba, Wb, bb, b0,
        eidx, v, p, Wc, batch, out_atoms, N, E, nodeBlocks, scatBlocks);

    // launch 1: fused edge network + coords finalize
    int edgeBlocks = (E + ETILE - 1) / ETILE;
    int finBlocks  = (N * 3 + 255) / 256;
    edge_kernel<<<edgeBlocks + finBlocks, 256, EDGE_SMEM_BYTES>>>(
        e, eidx, batch, W0, W1, b1, out_bonds, out_coords, N, E, edgeBlocks);

    // launch 2: self-clean g_map + zero sums for graph replay
    cleanup_kernel<<<(E + 255) / 256, 256>>>(eidx, N, E);
}